// round 1
// baseline (speedup 1.0000x reference)
#include <cuda_runtime.h>
#include <math.h>

// Problem constants
#define S_LEN   2048
#define DMODEL  1024
#define NHEADS  16
#define HDIM    64
#define BATCH   2
#define MROWS   (BATCH * S_LEN)   // 4096

// Scratch (no cudaMalloc allowed) — 4 x 16 MiB fp32
__device__ float g_Q[BATCH * NHEADS * S_LEN * HDIM];
__device__ float g_K[BATCH * NHEADS * S_LEN * HDIM];
__device__ float g_V[BATCH * NHEADS * S_LEN * HDIM];
__device__ float g_ctx[BATCH * S_LEN * DMODEL];

// ---------------------------------------------------------------------------
// Kernel 1: fused QKV projection.  Out = X @ W, written as [B,H,S,HD].
// 128x128 block tile, BK=16, 256 threads, 8x8 microtile.
// grid = (N/128, M/128, 3), z selects Wq/Wk/Wv.
// ---------------------------------------------------------------------------
__global__ __launch_bounds__(256) void qkv_proj_kernel(
    const float* __restrict__ X,
    const float* __restrict__ Wq,
    const float* __restrict__ Wk,
    const float* __restrict__ Wv)
{
    __shared__ __align__(16) float As[16][128];
    __shared__ __align__(16) float Bs[16][128];

    const float* W   = (blockIdx.z == 0) ? Wq : (blockIdx.z == 1) ? Wk : Wv;
    float*       Out = (blockIdx.z == 0) ? g_Q : (blockIdx.z == 1) ? g_K : g_V;

    const int tid = threadIdx.x;
    const int ty  = tid >> 4;        // 0..15
    const int tx  = tid & 15;        // 0..15
    const int rowBase = blockIdx.y * 128;
    const int colBase = blockIdx.x * 128;

    // A tile loader: 128 rows x 16 cols, float4
    const int aRow = tid >> 2;        // 0..63
    const int aCol = (tid & 3) * 4;   // 0,4,8,12
    // B tile loader: 16 rows x 128 cols, float4
    const int bRow = tid >> 5;        // 0..7
    const int bCol = (tid & 31) * 4;  // 0..124

    float acc[8][8];
#pragma unroll
    for (int i = 0; i < 8; i++)
#pragma unroll
        for (int j = 0; j < 8; j++) acc[i][j] = 0.f;

    for (int k0 = 0; k0 < DMODEL; k0 += 16) {
#pragma unroll
        for (int r = 0; r < 2; r++) {
            float4 v = *(const float4*)&X[(size_t)(rowBase + aRow + 64 * r) * DMODEL + k0 + aCol];
            As[aCol + 0][aRow + 64 * r] = v.x;
            As[aCol + 1][aRow + 64 * r] = v.y;
            As[aCol + 2][aRow + 64 * r] = v.z;
            As[aCol + 3][aRow + 64 * r] = v.w;
        }
#pragma unroll
        for (int r = 0; r < 2; r++) {
            float4 v = *(const float4*)&W[(size_t)(k0 + bRow + 8 * r) * DMODEL + colBase + bCol];
            *(float4*)&Bs[bRow + 8 * r][bCol] = v;
        }
        __syncthreads();

#pragma unroll
        for (int kk = 0; kk < 16; kk++) {
            float a[8], b[8];
            *(float4*)&a[0] = *(const float4*)&As[kk][ty * 8];
            *(float4*)&a[4] = *(const float4*)&As[kk][ty * 8 + 4];
            *(float4*)&b[0] = *(const float4*)&Bs[kk][tx * 8];
            *(float4*)&b[4] = *(const float4*)&Bs[kk][tx * 8 + 4];
#pragma unroll
            for (int i = 0; i < 8; i++)
#pragma unroll
                for (int j = 0; j < 8; j++)
                    acc[i][j] = fmaf(a[i], b[j], acc[i][j]);
        }
        __syncthreads();
    }

    // Scatter into [B,H,S,HD]
#pragma unroll
    for (int i = 0; i < 8; i++) {
        const int m = rowBase + ty * 8 + i;
        const int b = m >> 11;
        const int s = m & 2047;
#pragma unroll
        for (int j = 0; j < 8; j++) {
            const int n  = colBase + tx * 8 + j;
            const int h  = n >> 6;
            const int hd = n & 63;
            Out[(((size_t)b * NHEADS + h) * S_LEN + s) * HDIM + hd] = acc[i][j];
        }
    }
}

// ---------------------------------------------------------------------------
// Kernel 2: causal flash attention.  BM=BN=64, HD=64.
// grid = (S/64, B*H), 256 threads (16x16), 4x4 microtile.
// Dynamic smem: Qs[64][64] | KPs[64][65] (K tile, reused for P) | Vs[64][64]
// ---------------------------------------------------------------------------
#define ATTN_SMEM_FLOATS (64 * 64 + 64 * 65 + 64 * 64)   // 12352
#define ATTN_SMEM_BYTES  (ATTN_SMEM_FLOATS * 4)          // 49408

__global__ __launch_bounds__(256) void attn_kernel()
{
    extern __shared__ __align__(16) float smem[];
    float* Qs  = smem;                 // [m][hd], stride 64
    float* KPs = smem + 64 * 64;       // [key][hd] / [m][key], stride 65
    float* Vs  = KPs + 64 * 65;        // [key][hd], stride 64

    const int qt  = blockIdx.x;                  // query tile
    const int bh  = blockIdx.y;                  // b*H + h
    const float* Qg = g_Q + (size_t)bh * S_LEN * HDIM;
    const float* Kg = g_K + (size_t)bh * S_LEN * HDIM;
    const float* Vg = g_V + (size_t)bh * S_LEN * HDIM;

    const int tid = threadIdx.x;
    const int ty  = tid >> 4, tx = tid & 15;
    const int ty4 = ty * 4,  tx4 = tx * 4;

    const int lrow = tid >> 4;          // 0..15
    const int lc4  = (tid & 15) * 4;    // hd offset for loads

    // Load Q tile (rows qt*64 .. +63), natural layout
#pragma unroll
    for (int r = 0; r < 4; r++) {
        const int m = lrow + 16 * r;
        float4 v = *(const float4*)&Qg[(size_t)(qt * 64 + m) * HDIM + lc4];
        *(float4*)&Qs[m * 64 + lc4] = v;
    }

    float o[4][4];
#pragma unroll
    for (int i = 0; i < 4; i++)
#pragma unroll
        for (int j = 0; j < 4; j++) o[i][j] = 0.f;
    float m_i[4] = {-INFINITY, -INFINITY, -INFINITY, -INFINITY};
    float l_i[4] = {0.f, 0.f, 0.f, 0.f};

    for (int j = 0; j <= qt; j++) {
        __syncthreads();   // previous P/V consumers done; Q load visible on first iter after next sync
        // Load K and V tiles for key block j
#pragma unroll
        for (int r = 0; r < 4; r++) {
            const int m = lrow + 16 * r;
            float4 kv = *(const float4*)&Kg[(size_t)(j * 64 + m) * HDIM + lc4];
            KPs[m * 65 + lc4 + 0] = kv.x;
            KPs[m * 65 + lc4 + 1] = kv.y;
            KPs[m * 65 + lc4 + 2] = kv.z;
            KPs[m * 65 + lc4 + 3] = kv.w;
            float4 vv = *(const float4*)&Vg[(size_t)(j * 64 + m) * HDIM + lc4];
            *(float4*)&Vs[m * 64 + lc4] = vv;
        }
        __syncthreads();

        // S = Q K^T (64x64x64), 4x4 per thread
        float s[4][4];
#pragma unroll
        for (int i = 0; i < 4; i++)
#pragma unroll
            for (int jj = 0; jj < 4; jj++) s[i][jj] = 0.f;

#pragma unroll 8
        for (int k = 0; k < 64; k++) {
            float a[4], b[4];
#pragma unroll
            for (int i = 0; i < 4; i++) a[i] = Qs[(ty4 + i) * 64 + k];
#pragma unroll
            for (int jj = 0; jj < 4; jj++) b[jj] = KPs[(tx4 + jj) * 65 + k];
#pragma unroll
            for (int i = 0; i < 4; i++)
#pragma unroll
                for (int jj = 0; jj < 4; jj++)
                    s[i][jj] = fmaf(a[i], b[jj], s[i][jj]);
        }

        const float scale = 0.125f;   // HD^-0.5
        const bool diag = (j == qt);
#pragma unroll
        for (int i = 0; i < 4; i++)
#pragma unroll
            for (int jj = 0; jj < 4; jj++) {
                float v = s[i][jj] * scale;
                if (diag && (tx4 + jj > ty4 + i)) v = -1e30f;
                s[i][jj] = v;
            }

        __syncthreads();   // everyone done reading K before P overwrites it

        // Online softmax per row (rows shared across the 16 tx lanes)
#pragma unroll
        for (int i = 0; i < 4; i++) {
            float mt = s[i][0];
#pragma unroll
            for (int jj = 1; jj < 4; jj++) mt = fmaxf(mt, s[i][jj]);
#pragma unroll
            for (int off = 8; off > 0; off >>= 1)
                mt = fmaxf(mt, __shfl_xor_sync(0xffffffffu, mt, off, 16));
            const float m_new = fmaxf(m_i[i], mt);
            const float corr  = __expf(m_i[i] - m_new);
            float rs = 0.f;
#pragma unroll
            for (int jj = 0; jj < 4; jj++) {
                const float p = __expf(s[i][jj] - m_new);
                s[i][jj] = p;
                rs += p;
            }
#pragma unroll
            for (int off = 8; off > 0; off >>= 1)
                rs += __shfl_xor_sync(0xffffffffu, rs, off, 16);
            l_i[i] = l_i[i] * corr + rs;
#pragma unroll
            for (int jj = 0; jj < 4; jj++) o[i][jj] *= corr;
            m_i[i] = m_new;
            // write P row chunk
#pragma unroll
            for (int jj = 0; jj < 4; jj++)
                KPs[(ty4 + i) * 65 + tx4 + jj] = s[i][jj];
        }
        __syncthreads();

        // O += P @ V  (64x64x64)
#pragma unroll 8
        for (int k = 0; k < 64; k++) {
            float a[4];
#pragma unroll
            for (int i = 0; i < 4; i++) a[i] = KPs[(ty4 + i) * 65 + k];
            float4 bv = *(const float4*)&Vs[k * 64 + tx4];
#pragma unroll
            for (int i = 0; i < 4; i++) {
                o[i][0] = fmaf(a[i], bv.x, o[i][0]);
                o[i][1] = fmaf(a[i], bv.y, o[i][1]);
                o[i][2] = fmaf(a[i], bv.z, o[i][2]);
                o[i][3] = fmaf(a[i], bv.w, o[i][3]);
            }
        }
    }

    // Normalize and write ctx[b, s, h*64 + hd]
    const int b = bh >> 4;
    const int h = bh & 15;
#pragma unroll
    for (int i = 0; i < 4; i++) {
        const float inv_l = 1.f / l_i[i];
        const int sidx = qt * 64 + ty4 + i;
        float4 v;
        v.x = o[i][0] * inv_l;
        v.y = o[i][1] * inv_l;
        v.z = o[i][2] * inv_l;
        v.w = o[i][3] * inv_l;
        *(float4*)&g_ctx[((size_t)b * S_LEN + sidx) * DMODEL + h * HDIM + tx4] = v;
    }
}

// ---------------------------------------------------------------------------
// Kernel 3: output projection.  out = ctx @ Wo^T + bo   (NT GEMM)
// grid = (1024/128, 4096/128), same 128x128x16 tiling.
// ---------------------------------------------------------------------------
__global__ __launch_bounds__(256) void out_proj_kernel(
    const float* __restrict__ Wo,
    const float* __restrict__ bo,
    float* __restrict__ Outp)
{
    __shared__ __align__(16) float As[16][128];
    __shared__ __align__(16) float Bs[16][128];

    const int tid = threadIdx.x;
    const int ty  = tid >> 4, tx = tid & 15;
    const int rowBase = blockIdx.y * 128;
    const int colBase = blockIdx.x * 128;

    const int aRow = tid >> 2;
    const int aCol = (tid & 3) * 4;

    float acc[8][8];
#pragma unroll
    for (int i = 0; i < 8; i++)
#pragma unroll
        for (int j = 0; j < 8; j++) acc[i][j] = 0.f;

    for (int k0 = 0; k0 < DMODEL; k0 += 16) {
#pragma unroll
        for (int r = 0; r < 2; r++) {
            float4 v = *(const float4*)&g_ctx[(size_t)(rowBase + aRow + 64 * r) * DMODEL + k0 + aCol];
            As[aCol + 0][aRow + 64 * r] = v.x;
            As[aCol + 1][aRow + 64 * r] = v.y;
            As[aCol + 2][aRow + 64 * r] = v.z;
            As[aCol + 3][aRow + 64 * r] = v.w;
            // Wo row-major [out, in]; we need Bs[kk][n] = Wo[n][k]
            float4 w = *(const float4*)&Wo[(size_t)(colBase + aRow + 64 * r) * DMODEL + k0 + aCol];
            Bs[aCol + 0][aRow + 64 * r] = w.x;
            Bs[aCol + 1][aRow + 64 * r] = w.y;
            Bs[aCol + 2][aRow + 64 * r] = w.z;
            Bs[aCol + 3][aRow + 64 * r] = w.w;
        }
        __syncthreads();

#pragma unroll
        for (int kk = 0; kk < 16; kk++) {
            float a[8], bb[8];
            *(float4*)&a[0]  = *(const float4*)&As[kk][ty * 8];
            *(float4*)&a[4]  = *(const float4*)&As[kk][ty * 8 + 4];
            *(float4*)&bb[0] = *(const float4*)&Bs[kk][tx * 8];
            *(float4*)&bb[4] = *(const float4*)&Bs[kk][tx * 8 + 4];
#pragma unroll
            for (int i = 0; i < 8; i++)
#pragma unroll
                for (int j = 0; j < 8; j++)
                    acc[i][j] = fmaf(a[i], bb[j], acc[i][j]);
        }
        __syncthreads();
    }

#pragma unroll
    for (int i = 0; i < 8; i++) {
        const int m = rowBase + ty * 8 + i;
#pragma unroll
        for (int j = 0; j < 8; j++) {
            const int n = colBase + tx * 8 + j;
            Outp[(size_t)m * DMODEL + n] = acc[i][j] + bo[n];
        }
    }
}

// ---------------------------------------------------------------------------
extern "C" void kernel_launch(void* const* d_in, const int* in_sizes, int n_in,
                              void* d_out, int out_size)
{
    const float* x  = (const float*)d_in[0];
    const float* Wq = (const float*)d_in[1];
    const float* Wk = (const float*)d_in[2];
    const float* Wv = (const float*)d_in[3];
    const float* Wo = (const float*)d_in[4];
    const float* bo = (const float*)d_in[5];
    float* out = (float*)d_out;

    // attention kernel needs 49,408 B dynamic smem (> 48 KB default)
    static int attr_set = 0;
    if (!attr_set) {
        cudaFuncSetAttribute(attn_kernel,
                             cudaFuncAttributeMaxDynamicSharedMemorySize,
                             ATTN_SMEM_BYTES);
        attr_set = 1;
    }

    // 1) QKV projections
    {
        dim3 grid(DMODEL / 128, MROWS / 128, 3);
        qkv_proj_kernel<<<grid, 256>>>(x, Wq, Wk, Wv);
    }
    // 2) causal attention
    {
        dim3 grid(S_LEN / 64, BATCH * NHEADS);
        attn_kernel<<<grid, 256, ATTN_SMEM_BYTES>>>();
    }
    // 3) output projection + bias
    {
        dim3 grid(DMODEL / 128, MROWS / 128);
        out_proj_kernel<<<grid, 256>>>(Wo, bo, out);
    }
}

// round 6
// speedup vs baseline: 1.6356x; 1.6356x over previous
#include <cuda_runtime.h>
#include <cuda_bf16.h>
#include <math.h>
#include <stdint.h>

#define S_LEN   2048
#define DMODEL  1024
#define NHEADS  16
#define HDIM    64
#define BATCH   2
#define MROWS   (BATCH * S_LEN)   // 4096

// Single dynamic-smem symbol shared by all kernels
extern __shared__ __align__(128) float dyn_smem[];

// ---------------------------------------------------------------------------
// Global scratch (no cudaMalloc allowed)
// ---------------------------------------------------------------------------
__device__ __align__(128) __nv_bfloat16 g_Xhi[MROWS * DMODEL];
__device__ __align__(128) __nv_bfloat16 g_Xlo[MROWS * DMODEL];
__device__ __align__(128) __nv_bfloat16 g_Wthi[3 * DMODEL * DMODEL];  // W^T [n][k]
__device__ __align__(128) __nv_bfloat16 g_Wtlo[3 * DMODEL * DMODEL];
__device__ __align__(128) __nv_bfloat16 g_Wohi[DMODEL * DMODEL];      // Wo already [n][k]
__device__ __align__(128) __nv_bfloat16 g_Wolo[DMODEL * DMODEL];
__device__ __align__(128) __nv_bfloat16 g_Chi[MROWS * DMODEL];        // ctx split
__device__ __align__(128) __nv_bfloat16 g_Clo[MROWS * DMODEL];
__device__ float g_QKV[3 * MROWS * DMODEL];   // Q,K,V row-major [4096][1024] fp32

// ---------------------------------------------------------------------------
// Helpers
// ---------------------------------------------------------------------------
__device__ __forceinline__ uint32_t smem_u32(const void* p) {
    uint32_t a;
    asm("{ .reg .u64 t; cvta.to.shared.u64 t, %1; cvt.u32.u64 %0, t; }" : "=r"(a) : "l"(p));
    return a;
}
__device__ __forceinline__ void ldsm_x4(uint32_t* r, uint32_t addr) {
    asm volatile("ldmatrix.sync.aligned.m8n8.x4.shared.b16 {%0,%1,%2,%3}, [%4];"
                 : "=r"(r[0]), "=r"(r[1]), "=r"(r[2]), "=r"(r[3]) : "r"(addr));
}
__device__ __forceinline__ void mma_bf16(float* c, const uint32_t* a, uint32_t b0, uint32_t b1) {
    asm volatile(
        "mma.sync.aligned.m16n8k16.row.col.f32.bf16.bf16.f32 "
        "{%0,%1,%2,%3},{%4,%5,%6,%7},{%8,%9},{%0,%1,%2,%3};"
        : "+f"(c[0]), "+f"(c[1]), "+f"(c[2]), "+f"(c[3])
        : "r"(a[0]), "r"(a[1]), "r"(a[2]), "r"(a[3]), "r"(b0), "r"(b1));
}

// ---------------------------------------------------------------------------
// Pre-pass: bf16 hi/lo splits (+ transpose for Wq/Wk/Wv)
// ---------------------------------------------------------------------------
__global__ void split_kernel(const float* __restrict__ src, int n, int mode) {
    __nv_bfloat16* hi = mode ? g_Wohi : g_Xhi;
    __nv_bfloat16* lo = mode ? g_Wolo : g_Xlo;
    int i = blockIdx.x * 256 + threadIdx.x;
    if (i < n) {
        float a = src[i];
        __nv_bfloat16 h = __float2bfloat16(a);
        hi[i] = h;
        lo[i] = __float2bfloat16(a - __bfloat162float(h));
    }
}

__global__ void tsplit_kernel(const float* __restrict__ Wq,
                              const float* __restrict__ Wk,
                              const float* __restrict__ Wv) {
    const float* W = (blockIdx.z == 0) ? Wq : (blockIdx.z == 1) ? Wk : Wv;
    __nv_bfloat16* Hi = g_Wthi + (size_t)blockIdx.z * DMODEL * DMODEL;
    __nv_bfloat16* Lo = g_Wtlo + (size_t)blockIdx.z * DMODEL * DMODEL;
    __shared__ float t[32][33];
    const int k0 = blockIdx.y * 32, n0 = blockIdx.x * 32;
    const int tx = threadIdx.x, ty = threadIdx.y;   // 32 x 8
#pragma unroll
    for (int r = 0; r < 4; r++)
        t[ty + 8 * r][tx] = W[(size_t)(k0 + ty + 8 * r) * DMODEL + n0 + tx];
    __syncthreads();
#pragma unroll
    for (int r = 0; r < 4; r++) {
        float a = t[tx][ty + 8 * r];                // = W[k0+tx][n0+ty+8r]
        size_t idx = (size_t)(n0 + ty + 8 * r) * DMODEL + k0 + tx;
        __nv_bfloat16 h = __float2bfloat16(a);
        Hi[idx] = h;
        Lo[idx] = __float2bfloat16(a - __bfloat162float(h));
    }
}

// ---------------------------------------------------------------------------
// bf16 3x mma.sync GEMM: C[128x128 tile] = A(M,K) * B(N,K)^T (+bias)
// mode 0: QKV (blockIdx.z selects weight/output), mode 1: out-proj
// smem: 2 stages x {Ahi 16K | Alo 16K | Bhi 16K | Blo 16K} = 128 KB
// ---------------------------------------------------------------------------
#define GS_STAGE 65536
#define GS_AHI   0
#define GS_ALO   16384
#define GS_BHI   32768
#define GS_BLO   49152
#define GS_TOTAL (2 * GS_STAGE)   // 131072

// Load one 128-row x 64-col bf16 tile (row stride DMODEL) into swizzled smem.
// 128 rows x 128 bytes = 1024 x 16B chunks; 256 threads -> 4 iterations.
__device__ __forceinline__ void load_tile_bf16(uint32_t sdst, const __nv_bfloat16* g, int tid) {
#pragma unroll
    for (int t = 0; t < 4; t++) {
        int cid = t * 256 + tid;            // 0..1023
        int r = cid >> 3, ch = cid & 7;     // row 0..127, 16B-chunk 0..7
        uint32_t off = (uint32_t)(r * 128 + ch * 16);
        off ^= (off >> 3) & 0x70;           // SW128 swizzle
        const char* src = (const char*)(g + (size_t)r * DMODEL) + ch * 16;
        asm volatile("cp.async.cg.shared.global [%0], [%1], 16;" :: "r"(sdst + off), "l"(src));
    }
}

__global__ __launch_bounds__(256) void gemm_kernel(int mode, float* __restrict__ outp,
                                                   const float* __restrict__ biasp) {
    uint32_t sb = smem_u32(dyn_smem);
    const int tid = threadIdx.x, lane = tid & 31, wid = tid >> 5;
    const int wm = (wid >> 2) * 64, wn = (wid & 3) * 32;
    const int rowBase = blockIdx.y * 128;
    const int colBase = blockIdx.x * 128;
    const int z = blockIdx.z;

    const __nv_bfloat16 *Ah, *Al, *Bh, *Bl;
    const float* bias;
    float* C;
    if (mode == 0) {
        Ah = g_Xhi; Al = g_Xlo;
        Bh = g_Wthi + (size_t)z * DMODEL * DMODEL;
        Bl = g_Wtlo + (size_t)z * DMODEL * DMODEL;
        C  = g_QKV + (size_t)z * MROWS * DMODEL;
        bias = nullptr;
    } else {
        Ah = g_Chi; Al = g_Clo;
        Bh = g_Wohi; Bl = g_Wolo;
        C  = outp;
        bias = biasp;
    }
    Ah += (size_t)rowBase * DMODEL;
    Al += (size_t)rowBase * DMODEL;
    Bh += (size_t)colBase * DMODEL;
    Bl += (size_t)colBase * DMODEL;

    float c[4][4][4];
#pragma unroll
    for (int i = 0; i < 4; i++)
#pragma unroll
        for (int j = 0; j < 4; j++)
#pragma unroll
            for (int k = 0; k < 4; k++) c[i][j][k] = 0.f;

    // prologue: chunk 0 -> stage 0
    load_tile_bf16(sb + GS_AHI, Ah, tid);
    load_tile_bf16(sb + GS_ALO, Al, tid);
    load_tile_bf16(sb + GS_BHI, Bh, tid);
    load_tile_bf16(sb + GS_BLO, Bl, tid);
    asm volatile("cp.async.commit_group;");

    for (int ck = 0; ck < 16; ck++) {
        const int s = ck & 1;
        if (ck > 0) __syncthreads();   // prior-iteration consumers done before overwrite
        if (ck + 1 < 16) {
            uint32_t st = sb + (uint32_t)((ck + 1) & 1) * GS_STAGE;
            const int k0 = (ck + 1) * 64;
            load_tile_bf16(st + GS_AHI, Ah + k0, tid);
            load_tile_bf16(st + GS_ALO, Al + k0, tid);
            load_tile_bf16(st + GS_BHI, Bh + k0, tid);
            load_tile_bf16(st + GS_BLO, Bl + k0, tid);
            asm volatile("cp.async.commit_group;");
            asm volatile("cp.async.wait_group 1;");
        } else {
            asm volatile("cp.async.wait_group 0;");
        }
        __syncthreads();

        const uint32_t aHi = sb + (uint32_t)s * GS_STAGE + GS_AHI;
        const uint32_t aLo = sb + (uint32_t)s * GS_STAGE + GS_ALO;
        const uint32_t bHi = sb + (uint32_t)s * GS_STAGE + GS_BHI;
        const uint32_t bLo = sb + (uint32_t)s * GS_STAGE + GS_BLO;

        const int rA = lane & 15;
        const int cbBase = (lane >> 4) << 4;   // 0 or 16 bytes

#pragma unroll
        for (int ks = 0; ks < 4; ks++) {
            const int cb = ks * 32 + cbBase;
            uint32_t AhF[4][4], AlF[4][4], BhF[2][4], BlF[2][4];
#pragma unroll
            for (int mt = 0; mt < 4; mt++) {
                uint32_t off = (uint32_t)((wm + mt * 16 + rA) * 128 + cb);
                off ^= (off >> 3) & 0x70;
                ldsm_x4(AhF[mt], aHi + off);
                ldsm_x4(AlF[mt], aLo + off);
            }
#pragma unroll
            for (int np = 0; np < 2; np++) {
                uint32_t off = (uint32_t)((wn + np * 16 + rA) * 128 + cb);
                off ^= (off >> 3) & 0x70;
                ldsm_x4(BhF[np], bHi + off);
                ldsm_x4(BlF[np], bLo + off);
            }
#pragma unroll
            for (int mt = 0; mt < 4; mt++) {
#pragma unroll
                for (int nt = 0; nt < 4; nt++) {
                    const int np = nt >> 1, o = nt & 1;
                    mma_bf16(c[mt][nt], AhF[mt], BhF[np][o], BhF[np][o + 2]);
                    mma_bf16(c[mt][nt], AhF[mt], BlF[np][o], BlF[np][o + 2]);
                    mma_bf16(c[mt][nt], AlF[mt], BhF[np][o], BhF[np][o + 2]);
                }
            }
        }
    }

    // epilogue: direct fp32 stores (float2)
    const int r0l = lane >> 2, cl = 2 * (lane & 3);
#pragma unroll
    for (int mt = 0; mt < 4; mt++) {
#pragma unroll
        for (int nt = 0; nt < 4; nt++) {
            const int r0 = rowBase + wm + mt * 16 + r0l;
            const int col = colBase + wn + nt * 8 + cl;
            float2 v0 = make_float2(c[mt][nt][0], c[mt][nt][1]);
            float2 v1 = make_float2(c[mt][nt][2], c[mt][nt][3]);
            if (bias) {
                const float b0 = bias[col], b1 = bias[col + 1];
                v0.x += b0; v0.y += b1;
                v1.x += b0; v1.y += b1;
            }
            *(float2*)&C[(size_t)r0 * DMODEL + col] = v0;
            *(float2*)&C[(size_t)(r0 + 8) * DMODEL + col] = v1;
        }
    }
}

// ---------------------------------------------------------------------------
// Causal flash attention (fp32 FFMA; row-major QKV; epilogue -> bf16 hi/lo ctx)
// ---------------------------------------------------------------------------
#define ATTN_SMEM_FLOATS (64 * 64 + 64 * 65 + 64 * 64)
#define ATTN_SMEM_BYTES  (ATTN_SMEM_FLOATS * 4)

__global__ __launch_bounds__(256) void attn_kernel() {
    float* Qs  = dyn_smem;
    float* KPs = dyn_smem + 64 * 64;
    float* Vs  = KPs + 64 * 65;

    const int qt = blockIdx.x;
    const int bh = blockIdx.y;
    const int b = bh >> 4;
    const int h = bh & 15;
    const size_t bhoff = (size_t)b * S_LEN * DMODEL + (size_t)h * HDIM;
    const float* Qg = g_QKV + bhoff;
    const float* Kg = g_QKV + (size_t)MROWS * DMODEL + bhoff;
    const float* Vg = g_QKV + (size_t)2 * MROWS * DMODEL + bhoff;

    const int tid = threadIdx.x;
    const int ty = tid >> 4, tx = tid & 15;
    const int ty4 = ty * 4, tx4 = tx * 4;
    const int lrow = tid >> 4;
    const int lc4 = (tid & 15) * 4;

#pragma unroll
    for (int r = 0; r < 4; r++) {
        const int m = lrow + 16 * r;
        float4 v = *(const float4*)&Qg[(size_t)(qt * 64 + m) * DMODEL + lc4];
        *(float4*)&Qs[m * 64 + lc4] = v;
    }

    float o[4][4];
#pragma unroll
    for (int i = 0; i < 4; i++)
#pragma unroll
        for (int j = 0; j < 4; j++) o[i][j] = 0.f;
    float m_i[4] = {-INFINITY, -INFINITY, -INFINITY, -INFINITY};
    float l_i[4] = {0.f, 0.f, 0.f, 0.f};

    for (int j = 0; j <= qt; j++) {
        __syncthreads();
#pragma unroll
        for (int r = 0; r < 4; r++) {
            const int m = lrow + 16 * r;
            float4 kv = *(const float4*)&Kg[(size_t)(j * 64 + m) * DMODEL + lc4];
            KPs[m * 65 + lc4 + 0] = kv.x;
            KPs[m * 65 + lc4 + 1] = kv.y;
            KPs[m * 65 + lc4 + 2] = kv.z;
            KPs[m * 65 + lc4 + 3] = kv.w;
            float4 vv = *(const float4*)&Vg[(size_t)(j * 64 + m) * DMODEL + lc4];
            *(float4*)&Vs[m * 64 + lc4] = vv;
        }
        __syncthreads();

        float s[4][4];
#pragma unroll
        for (int i = 0; i < 4; i++)
#pragma unroll
            for (int jj = 0; jj < 4; jj++) s[i][jj] = 0.f;

#pragma unroll 8
        for (int k = 0; k < 64; k++) {
            float a[4], bb[4];
#pragma unroll
            for (int i = 0; i < 4; i++) a[i] = Qs[(ty4 + i) * 64 + k];
#pragma unroll
            for (int jj = 0; jj < 4; jj++) bb[jj] = KPs[(tx4 + jj) * 65 + k];
#pragma unroll
            for (int i = 0; i < 4; i++)
#pragma unroll
                for (int jj = 0; jj < 4; jj++)
                    s[i][jj] = fmaf(a[i], bb[jj], s[i][jj]);
        }

        const float scale = 0.125f;
        const bool diag = (j == qt);
#pragma unroll
        for (int i = 0; i < 4; i++)
#pragma unroll
            for (int jj = 0; jj < 4; jj++) {
                float v = s[i][jj] * scale;
                if (diag && (tx4 + jj > ty4 + i)) v = -1e30f;
                s[i][jj] = v;
            }

        __syncthreads();

#pragma unroll
        for (int i = 0; i < 4; i++) {
            float mt = s[i][0];
#pragma unroll
            for (int jj = 1; jj < 4; jj++) mt = fmaxf(mt, s[i][jj]);
#pragma unroll
            for (int off = 8; off > 0; off >>= 1)
                mt = fmaxf(mt, __shfl_xor_sync(0xffffffffu, mt, off, 16));
            const float m_new = fmaxf(m_i[i], mt);
            const float corr = __expf(m_i[i] - m_new);
            float rs = 0.f;
#pragma unroll
            for (int jj = 0; jj < 4; jj++) {
                const float p = __expf(s[i][jj] - m_new);
                s[i][jj] = p;
                rs += p;
            }
#pragma unroll
            for (int off = 8; off > 0; off >>= 1)
                rs += __shfl_xor_sync(0xffffffffu, rs, off, 16);
            l_i[i] = l_i[i] * corr + rs;
#pragma unroll
            for (int jj = 0; jj < 4; jj++) o[i][jj] *= corr;
            m_i[i] = m_new;
#pragma unroll
            for (int jj = 0; jj < 4; jj++)
                KPs[(ty4 + i) * 65 + tx4 + jj] = s[i][jj];
        }
        __syncthreads();

#pragma unroll 8
        for (int k = 0; k < 64; k++) {
            float a[4];
#pragma unroll
            for (int i = 0; i < 4; i++) a[i] = KPs[(ty4 + i) * 65 + k];
            float4 bv = *(const float4*)&Vs[k * 64 + tx4];
#pragma unroll
            for (int i = 0; i < 4; i++) {
                o[i][0] = fmaf(a[i], bv.x, o[i][0]);
                o[i][1] = fmaf(a[i], bv.y, o[i][1]);
                o[i][2] = fmaf(a[i], bv.z, o[i][2]);
                o[i][3] = fmaf(a[i], bv.w, o[i][3]);
            }
        }
    }

    // ctx -> bf16 hi/lo split, row-major [4096][1024]
#pragma unroll
    for (int i = 0; i < 4; i++) {
        const float inv_l = 1.f / l_i[i];
        const int sidx = qt * 64 + ty4 + i;
        const size_t base = ((size_t)b * S_LEN + sidx) * DMODEL + h * HDIM + tx4;
        __nv_bfloat162 h01, h23, l01, l23;
        float v, hf;
        __nv_bfloat16 hb;
        v = o[i][0] * inv_l; hb = __float2bfloat16(v); hf = __bfloat162float(hb);
        h01.x = hb; l01.x = __float2bfloat16(v - hf);
        v = o[i][1] * inv_l; hb = __float2bfloat16(v); hf = __bfloat162float(hb);
        h01.y = hb; l01.y = __float2bfloat16(v - hf);
        v = o[i][2] * inv_l; hb = __float2bfloat16(v); hf = __bfloat162float(hb);
        h23.x = hb; l23.x = __float2bfloat16(v - hf);
        v = o[i][3] * inv_l; hb = __float2bfloat16(v); hf = __bfloat162float(hb);
        h23.y = hb; l23.y = __float2bfloat16(v - hf);
        *(__nv_bfloat162*)&g_Chi[base]     = h01;
        *(__nv_bfloat162*)&g_Chi[base + 2] = h23;
        *(__nv_bfloat162*)&g_Clo[base]     = l01;
        *(__nv_bfloat162*)&g_Clo[base + 2] = l23;
    }
}

// ---------------------------------------------------------------------------
extern "C" void kernel_launch(void* const* d_in, const int* in_sizes, int n_in,
                              void* d_out, int out_size)
{
    const float* x  = (const float*)d_in[0];
    const float* Wq = (const float*)d_in[1];
    const float* Wk = (const float*)d_in[2];
    const float* Wv = (const float*)d_in[3];
    const float* Wo = (const float*)d_in[4];
    const float* bo = (const float*)d_in[5];
    float* out = (float*)d_out;

    cudaFuncSetAttribute(gemm_kernel, cudaFuncAttributeMaxDynamicSharedMemorySize, GS_TOTAL);
    cudaFuncSetAttribute(attn_kernel, cudaFuncAttributeMaxDynamicSharedMemorySize, ATTN_SMEM_BYTES);

    // 1) bf16 hi/lo pre-splits
    split_kernel<<<(MROWS * DMODEL + 255) / 256, 256>>>(x, MROWS * DMODEL, 0);
    split_kernel<<<(DMODEL * DMODEL + 255) / 256, 256>>>(Wo, DMODEL * DMODEL, 1);
    tsplit_kernel<<<dim3(32, 32, 3), dim3(32, 8)>>>(Wq, Wk, Wv);

    // 2) QKV projections (bf16 3x mma.sync)
    gemm_kernel<<<dim3(DMODEL / 128, MROWS / 128, 3), 256, GS_TOTAL>>>(0, nullptr, nullptr);

    // 3) causal attention (fp32)
    attn_kernel<<<dim3(S_LEN / 64, BATCH * NHEADS), 256, ATTN_SMEM_BYTES>>>();

    // 4) output projection + bias (bf16 3x mma.sync)
    gemm_kernel<<<dim3(DMODEL / 128, MROWS / 128, 1), 256, GS_TOTAL>>>(1, out, bo);
}

// round 8
// speedup vs baseline: 2.8877x; 1.7655x over previous
#include <cuda_runtime.h>
#include <cuda_bf16.h>
#include <math.h>
#include <stdint.h>

#define S_LEN   2048
#define DMODEL  1024
#define NHEADS  16
#define HDIM    64
#define BATCH   2
#define MROWS   (BATCH * S_LEN)   // 4096

extern __shared__ __align__(128) float dyn_smem[];

// ---------------------------------------------------------------------------
// Global scratch
// ---------------------------------------------------------------------------
__device__ __align__(128) __nv_bfloat16 g_Xhi[MROWS * DMODEL];
__device__ __align__(128) __nv_bfloat16 g_Xlo[MROWS * DMODEL];
__device__ __align__(128) __nv_bfloat16 g_Wthi[3 * DMODEL * DMODEL];
__device__ __align__(128) __nv_bfloat16 g_Wtlo[3 * DMODEL * DMODEL];
__device__ __align__(128) __nv_bfloat16 g_Wohi[DMODEL * DMODEL];
__device__ __align__(128) __nv_bfloat16 g_Wolo[DMODEL * DMODEL];
__device__ __align__(128) __nv_bfloat16 g_Chi[MROWS * DMODEL];
__device__ __align__(128) __nv_bfloat16 g_Clo[MROWS * DMODEL];
__device__ __align__(128) __nv_bfloat16 g_QKVhi[3 * MROWS * DMODEL];  // Q pre-scaled by 0.125
__device__ __align__(128) __nv_bfloat16 g_QKVlo[3 * MROWS * DMODEL];

// ---------------------------------------------------------------------------
// Helpers
// ---------------------------------------------------------------------------
__device__ __forceinline__ uint32_t smem_u32(const void* p) {
    uint32_t a;
    asm("{ .reg .u64 t; cvta.to.shared.u64 t, %1; cvt.u32.u64 %0, t; }" : "=r"(a) : "l"(p));
    return a;
}
__device__ __forceinline__ void ldsm_x4(uint32_t* r, uint32_t addr) {
    asm volatile("ldmatrix.sync.aligned.m8n8.x4.shared.b16 {%0,%1,%2,%3}, [%4];"
                 : "=r"(r[0]), "=r"(r[1]), "=r"(r[2]), "=r"(r[3]) : "r"(addr));
}
__device__ __forceinline__ void ldsm_x4_t(uint32_t* r, uint32_t addr) {
    asm volatile("ldmatrix.sync.aligned.m8n8.x4.trans.shared.b16 {%0,%1,%2,%3}, [%4];"
                 : "=r"(r[0]), "=r"(r[1]), "=r"(r[2]), "=r"(r[3]) : "r"(addr));
}
__device__ __forceinline__ void mma_bf16(float* c, const uint32_t* a, uint32_t b0, uint32_t b1) {
    asm volatile(
        "mma.sync.aligned.m16n8k16.row.col.f32.bf16.bf16.f32 "
        "{%0,%1,%2,%3},{%4,%5,%6,%7},{%8,%9},{%0,%1,%2,%3};"
        : "+f"(c[0]), "+f"(c[1]), "+f"(c[2]), "+f"(c[3])
        : "r"(a[0]), "r"(a[1]), "r"(a[2]), "r"(a[3]), "r"(b0), "r"(b1));
}
// split-pack: out_hi/out_lo get bf16 hi/lo pairs of (a,b)
__device__ __forceinline__ void split_pack(float a, float b, uint32_t& oh, uint32_t& ol) {
    __nv_bfloat16 ha = __float2bfloat16(a), hb = __float2bfloat16(b);
    float la = a - __bfloat162float(ha), lb = b - __bfloat162float(hb);
    __nv_bfloat162 th, tl;
    th.x = ha; th.y = hb;
    tl.x = __float2bfloat16(la); tl.y = __float2bfloat16(lb);
    oh = *(uint32_t*)&th; ol = *(uint32_t*)&tl;
}

// ---------------------------------------------------------------------------
// Pre-pass splits
// ---------------------------------------------------------------------------
__global__ void split_kernel(const float* __restrict__ src, int n, int mode) {
    __nv_bfloat16* hi = mode ? g_Wohi : g_Xhi;
    __nv_bfloat16* lo = mode ? g_Wolo : g_Xlo;
    int i = blockIdx.x * 256 + threadIdx.x;
    if (i < n) {
        float a = src[i];
        __nv_bfloat16 h = __float2bfloat16(a);
        hi[i] = h;
        lo[i] = __float2bfloat16(a - __bfloat162float(h));
    }
}

__global__ void tsplit_kernel(const float* __restrict__ Wq,
                              const float* __restrict__ Wk,
                              const float* __restrict__ Wv) {
    const float* W = (blockIdx.z == 0) ? Wq : (blockIdx.z == 1) ? Wk : Wv;
    __nv_bfloat16* Hi = g_Wthi + (size_t)blockIdx.z * DMODEL * DMODEL;
    __nv_bfloat16* Lo = g_Wtlo + (size_t)blockIdx.z * DMODEL * DMODEL;
    __shared__ float t[32][33];
    const int k0 = blockIdx.y * 32, n0 = blockIdx.x * 32;
    const int tx = threadIdx.x, ty = threadIdx.y;
#pragma unroll
    for (int r = 0; r < 4; r++)
        t[ty + 8 * r][tx] = W[(size_t)(k0 + ty + 8 * r) * DMODEL + n0 + tx];
    __syncthreads();
#pragma unroll
    for (int r = 0; r < 4; r++) {
        float a = t[tx][ty + 8 * r];
        size_t idx = (size_t)(n0 + ty + 8 * r) * DMODEL + k0 + tx;
        __nv_bfloat16 h = __float2bfloat16(a);
        Hi[idx] = h;
        Lo[idx] = __float2bfloat16(a - __bfloat162float(h));
    }
}

// ---------------------------------------------------------------------------
// bf16 3x mma GEMM. mode 0: QKV -> bf16 hi/lo (Q scaled); mode 1: out-proj.
// ---------------------------------------------------------------------------
#define GS_STAGE 65536
#define GS_AHI   0
#define GS_ALO   16384
#define GS_BHI   32768
#define GS_BLO   49152
#define GS_TOTAL (2 * GS_STAGE)

__device__ __forceinline__ void load_tile_bf16(uint32_t sdst, const __nv_bfloat16* g, int tid) {
#pragma unroll
    for (int t = 0; t < 4; t++) {
        int cid = t * 256 + tid;
        int r = cid >> 3, ch = cid & 7;
        uint32_t off = (uint32_t)(r * 128 + ch * 16);
        off ^= (off >> 3) & 0x70;
        const char* src = (const char*)(g + (size_t)r * DMODEL) + ch * 16;
        asm volatile("cp.async.cg.shared.global [%0], [%1], 16;" :: "r"(sdst + off), "l"(src));
    }
}

__global__ __launch_bounds__(256) void gemm_kernel(int mode, float* __restrict__ outp,
                                                   const float* __restrict__ biasp) {
    uint32_t sb = smem_u32(dyn_smem);
    const int tid = threadIdx.x, lane = tid & 31, wid = tid >> 5;
    const int wm = (wid >> 2) * 64, wn = (wid & 3) * 32;
    const int rowBase = blockIdx.y * 128;
    const int colBase = blockIdx.x * 128;
    const int z = blockIdx.z;

    const __nv_bfloat16 *Ah, *Al, *Bh, *Bl;
    if (mode == 0) {
        Ah = g_Xhi; Al = g_Xlo;
        Bh = g_Wthi + (size_t)z * DMODEL * DMODEL;
        Bl = g_Wtlo + (size_t)z * DMODEL * DMODEL;
    } else {
        Ah = g_Chi; Al = g_Clo;
        Bh = g_Wohi; Bl = g_Wolo;
    }
    Ah += (size_t)rowBase * DMODEL;
    Al += (size_t)rowBase * DMODEL;
    Bh += (size_t)colBase * DMODEL;
    Bl += (size_t)colBase * DMODEL;

    float c[4][4][4];
#pragma unroll
    for (int i = 0; i < 4; i++)
#pragma unroll
        for (int j = 0; j < 4; j++)
#pragma unroll
            for (int k = 0; k < 4; k++) c[i][j][k] = 0.f;

    load_tile_bf16(sb + GS_AHI, Ah, tid);
    load_tile_bf16(sb + GS_ALO, Al, tid);
    load_tile_bf16(sb + GS_BHI, Bh, tid);
    load_tile_bf16(sb + GS_BLO, Bl, tid);
    asm volatile("cp.async.commit_group;");

    for (int ck = 0; ck < 16; ck++) {
        const int s = ck & 1;
        if (ck > 0) __syncthreads();
        if (ck + 1 < 16) {
            uint32_t st = sb + (uint32_t)((ck + 1) & 1) * GS_STAGE;
            const int k0 = (ck + 1) * 64;
            load_tile_bf16(st + GS_AHI, Ah + k0, tid);
            load_tile_bf16(st + GS_ALO, Al + k0, tid);
            load_tile_bf16(st + GS_BHI, Bh + k0, tid);
            load_tile_bf16(st + GS_BLO, Bl + k0, tid);
            asm volatile("cp.async.commit_group;");
            asm volatile("cp.async.wait_group 1;");
        } else {
            asm volatile("cp.async.wait_group 0;");
        }
        __syncthreads();

        const uint32_t aHi = sb + (uint32_t)s * GS_STAGE + GS_AHI;
        const uint32_t aLo = sb + (uint32_t)s * GS_STAGE + GS_ALO;
        const uint32_t bHi = sb + (uint32_t)s * GS_STAGE + GS_BHI;
        const uint32_t bLo = sb + (uint32_t)s * GS_STAGE + GS_BLO;
        const int rA = lane & 15;
        const int cbBase = (lane >> 4) << 4;

#pragma unroll
        for (int ks = 0; ks < 4; ks++) {
            const int cb = ks * 32 + cbBase;
            uint32_t AhF[4][4], AlF[4][4], BhF[2][4], BlF[2][4];
#pragma unroll
            for (int mt = 0; mt < 4; mt++) {
                uint32_t off = (uint32_t)((wm + mt * 16 + rA) * 128 + cb);
                off ^= (off >> 3) & 0x70;
                ldsm_x4(AhF[mt], aHi + off);
                ldsm_x4(AlF[mt], aLo + off);
            }
#pragma unroll
            for (int np = 0; np < 2; np++) {
                uint32_t off = (uint32_t)((wn + np * 16 + rA) * 128 + cb);
                off ^= (off >> 3) & 0x70;
                ldsm_x4(BhF[np], bHi + off);
                ldsm_x4(BlF[np], bLo + off);
            }
#pragma unroll
            for (int mt = 0; mt < 4; mt++) {
#pragma unroll
                for (int nt = 0; nt < 4; nt++) {
                    const int np = nt >> 1, o = nt & 1;
                    mma_bf16(c[mt][nt], AhF[mt], BhF[np][o], BhF[np][o + 2]);
                    mma_bf16(c[mt][nt], AhF[mt], BlF[np][o], BlF[np][o + 2]);
                    mma_bf16(c[mt][nt], AlF[mt], BhF[np][o], BhF[np][o + 2]);
                }
            }
        }
    }

    const int r0l = lane >> 2, cl = 2 * (lane & 3);
    if (mode == 0) {
        const float scale = (z == 0) ? 0.125f : 1.0f;   // fold softmax scale into Q (exact)
        __nv_bfloat16* Hi = g_QKVhi + (size_t)z * MROWS * DMODEL;
        __nv_bfloat16* Lo = g_QKVlo + (size_t)z * MROWS * DMODEL;
#pragma unroll
        for (int mt = 0; mt < 4; mt++) {
#pragma unroll
            for (int nt = 0; nt < 4; nt++) {
                const int r0 = rowBase + wm + mt * 16 + r0l;
                const int col = colBase + wn + nt * 8 + cl;
                uint32_t h0, l0, h1, l1;
                split_pack(c[mt][nt][0] * scale, c[mt][nt][1] * scale, h0, l0);
                split_pack(c[mt][nt][2] * scale, c[mt][nt][3] * scale, h1, l1);
                *(uint32_t*)&Hi[(size_t)r0 * DMODEL + col] = h0;
                *(uint32_t*)&Lo[(size_t)r0 * DMODEL + col] = l0;
                *(uint32_t*)&Hi[(size_t)(r0 + 8) * DMODEL + col] = h1;
                *(uint32_t*)&Lo[(size_t)(r0 + 8) * DMODEL + col] = l1;
            }
        }
    } else {
#pragma unroll
        for (int mt = 0; mt < 4; mt++) {
#pragma unroll
            for (int nt = 0; nt < 4; nt++) {
                const int r0 = rowBase + wm + mt * 16 + r0l;
                const int col = colBase + wn + nt * 8 + cl;
                const float b0 = biasp[col], b1 = biasp[col + 1];
                float2 v0 = make_float2(c[mt][nt][0] + b0, c[mt][nt][1] + b1);
                float2 v1 = make_float2(c[mt][nt][2] + b0, c[mt][nt][3] + b1);
                *(float2*)&outp[(size_t)r0 * DMODEL + col] = v0;
                *(float2*)&outp[(size_t)(r0 + 8) * DMODEL + col] = v1;
            }
        }
    }
}

// ---------------------------------------------------------------------------
// Tensor-core causal flash attention.
// CTA: 128 q-rows x 1 head. 8 warps x m16. Key tiles of 64.
// smem: [stage0 KV 32K][stage1 KV 32K][Qhi 16K][Qlo 16K] = 96K
// ---------------------------------------------------------------------------
#define AT_STAGE 32768
#define AT_KHI   0
#define AT_KLO   8192
#define AT_VHI   16384
#define AT_VLO   24576
#define AT_QHI   65536
#define AT_QLO   81920
#define AT_TOTAL 98304

__device__ __forceinline__ void at_load64(uint32_t sdst, const __nv_bfloat16* g, int tid) {
#pragma unroll
    for (int t = 0; t < 2; t++) {
        int cid = t * 256 + tid;            // 0..511
        int r = cid >> 3, ch = cid & 7;     // 64 rows x 8 chunks
        uint32_t off = (uint32_t)(r * 128 + ch * 16);
        off ^= (off >> 3) & 0x70;
        const char* src = (const char*)(g + (size_t)r * DMODEL) + ch * 16;
        asm volatile("cp.async.cg.shared.global [%0], [%1], 16;" :: "r"(sdst + off), "l"(src));
    }
}
__device__ __forceinline__ void at_load128(uint32_t sdst, const __nv_bfloat16* g, int tid) {
#pragma unroll
    for (int t = 0; t < 4; t++) {
        int cid = t * 256 + tid;            // 0..1023
        int r = cid >> 3, ch = cid & 7;
        uint32_t off = (uint32_t)(r * 128 + ch * 16);
        off ^= (off >> 3) & 0x70;
        const char* src = (const char*)(g + (size_t)r * DMODEL) + ch * 16;
        asm volatile("cp.async.cg.shared.global [%0], [%1], 16;" :: "r"(sdst + off), "l"(src));
    }
}

__global__ __launch_bounds__(256) void attn_kernel() {
    uint32_t sb = smem_u32(dyn_smem);
    const int tid = threadIdx.x, lane = tid & 31, wid = tid >> 5;
    const int qt = blockIdx.x, bh = blockIdx.y;
    const int b = bh >> 4, h = bh & 15;
    const int wm = wid * 16;
    const int rA = lane & 15, cb16 = (lane >> 4) << 4;
    const int jmax = 2 * qt + 1;

    const size_t qoff = ((size_t)b * S_LEN + qt * 128) * DMODEL + h * HDIM;
    const __nv_bfloat16* Qh_g = g_QKVhi + qoff;
    const __nv_bfloat16* Ql_g = g_QKVlo + qoff;
    const size_t kvbase = (size_t)b * S_LEN * DMODEL + h * HDIM;
    const __nv_bfloat16* Kh_g = g_QKVhi + (size_t)MROWS * DMODEL + kvbase;
    const __nv_bfloat16* Kl_g = g_QKVlo + (size_t)MROWS * DMODEL + kvbase;
    const __nv_bfloat16* Vh_g = g_QKVhi + (size_t)2 * MROWS * DMODEL + kvbase;
    const __nv_bfloat16* Vl_g = g_QKVlo + (size_t)2 * MROWS * DMODEL + kvbase;

    at_load128(sb + AT_QHI, Qh_g, tid);
    at_load128(sb + AT_QLO, Ql_g, tid);
    at_load64(sb + AT_KHI, Kh_g, tid);
    at_load64(sb + AT_KLO, Kl_g, tid);
    at_load64(sb + AT_VHI, Vh_g, tid);
    at_load64(sb + AT_VLO, Vl_g, tid);
    asm volatile("cp.async.commit_group;");

    float co[8][4];
#pragma unroll
    for (int i = 0; i < 8; i++)
#pragma unroll
        for (int j = 0; j < 4; j++) co[i][j] = 0.f;
    float m_i[2] = {-INFINITY, -INFINITY};
    float l_i[2] = {0.f, 0.f};
    uint32_t QhF[4][4], QlF[4][4];

    for (int j = 0; j <= jmax; j++) {
        __syncthreads();
        if (j + 1 <= jmax) {
            uint32_t st = sb + (uint32_t)((j + 1) & 1) * AT_STAGE;
            const size_t ro = (size_t)(j + 1) * 64 * DMODEL;
            at_load64(st + AT_KHI, Kh_g + ro, tid);
            at_load64(st + AT_KLO, Kl_g + ro, tid);
            at_load64(st + AT_VHI, Vh_g + ro, tid);
            at_load64(st + AT_VLO, Vl_g + ro, tid);
            asm volatile("cp.async.commit_group;");
            asm volatile("cp.async.wait_group 1;");
        } else {
            asm volatile("cp.async.wait_group 0;");
        }
        __syncthreads();

        if (j == 0) {
#pragma unroll
            for (int ks = 0; ks < 4; ks++) {
                uint32_t off = (uint32_t)((wm + rA) * 128 + ks * 32 + cb16);
                off ^= (off >> 3) & 0x70;
                ldsm_x4(QhF[ks], sb + AT_QHI + off);
                ldsm_x4(QlF[ks], sb + AT_QLO + off);
            }
        }

        const int qmin = qt * 128 + wm;
        if (j * 64 > qmin + 15) continue;

        const uint32_t st = sb + (uint32_t)(j & 1) * AT_STAGE;

        // ---- S = Q K^T ----
        float cs[8][4];
#pragma unroll
        for (int i = 0; i < 8; i++)
#pragma unroll
            for (int e = 0; e < 4; e++) cs[i][e] = 0.f;
#pragma unroll
        for (int ks = 0; ks < 4; ks++) {
#pragma unroll
            for (int nt = 0; nt < 4; nt++) {
                uint32_t kh[4], kl[4];
                uint32_t off = (uint32_t)((nt * 16 + rA) * 128 + ks * 32 + cb16);
                off ^= (off >> 3) & 0x70;
                ldsm_x4(kh, st + AT_KHI + off);
                ldsm_x4(kl, st + AT_KLO + off);
#pragma unroll
                for (int o = 0; o < 2; o++) {
                    mma_bf16(cs[nt * 2 + o], QhF[ks], kh[o], kh[o + 2]);
                    mma_bf16(cs[nt * 2 + o], QhF[ks], kl[o], kl[o + 2]);
                    mma_bf16(cs[nt * 2 + o], QlF[ks], kh[o], kh[o + 2]);
                }
            }
        }

        // ---- causal mask ----
        if (j * 64 + 63 > qmin) {
            const int r0 = lane >> 2, c0 = 2 * (lane & 3);
#pragma unroll
            for (int nf = 0; nf < 8; nf++) {
#pragma unroll
                for (int e = 0; e < 4; e++) {
                    const int col = nf * 8 + c0 + (e & 1);
                    const int row = r0 + ((e >> 1) * 8);
                    if (j * 64 + col > qmin + row) cs[nf][e] = -1e30f;
                }
            }
        }

        // ---- online softmax ----
        float mx0 = -INFINITY, mx1 = -INFINITY;
#pragma unroll
        for (int nf = 0; nf < 8; nf++) {
            mx0 = fmaxf(mx0, fmaxf(cs[nf][0], cs[nf][1]));
            mx1 = fmaxf(mx1, fmaxf(cs[nf][2], cs[nf][3]));
        }
        mx0 = fmaxf(mx0, __shfl_xor_sync(0xffffffffu, mx0, 1));
        mx0 = fmaxf(mx0, __shfl_xor_sync(0xffffffffu, mx0, 2));
        mx1 = fmaxf(mx1, __shfl_xor_sync(0xffffffffu, mx1, 1));
        mx1 = fmaxf(mx1, __shfl_xor_sync(0xffffffffu, mx1, 2));
        const float mn0 = fmaxf(m_i[0], mx0), mn1 = fmaxf(m_i[1], mx1);
        const float corr0 = __expf(m_i[0] - mn0), corr1 = __expf(m_i[1] - mn1);
        float rs0 = 0.f, rs1 = 0.f;
#pragma unroll
        for (int nf = 0; nf < 8; nf++) {
            cs[nf][0] = __expf(cs[nf][0] - mn0); rs0 += cs[nf][0];
            cs[nf][1] = __expf(cs[nf][1] - mn0); rs0 += cs[nf][1];
            cs[nf][2] = __expf(cs[nf][2] - mn1); rs1 += cs[nf][2];
            cs[nf][3] = __expf(cs[nf][3] - mn1); rs1 += cs[nf][3];
        }
        rs0 += __shfl_xor_sync(0xffffffffu, rs0, 1);
        rs0 += __shfl_xor_sync(0xffffffffu, rs0, 2);
        rs1 += __shfl_xor_sync(0xffffffffu, rs1, 1);
        rs1 += __shfl_xor_sync(0xffffffffu, rs1, 2);
        l_i[0] = l_i[0] * corr0 + rs0; m_i[0] = mn0;
        l_i[1] = l_i[1] * corr1 + rs1; m_i[1] = mn1;
#pragma unroll
        for (int nf = 0; nf < 8; nf++) {
            co[nf][0] *= corr0; co[nf][1] *= corr0;
            co[nf][2] *= corr1; co[nf][3] *= corr1;
        }

        // ---- O += P V ----
#pragma unroll
        for (int kt = 0; kt < 4; kt++) {
            uint32_t pah[4], pal[4];
            split_pack(cs[2 * kt][0],     cs[2 * kt][1],     pah[0], pal[0]);
            split_pack(cs[2 * kt][2],     cs[2 * kt][3],     pah[1], pal[1]);
            split_pack(cs[2 * kt + 1][0], cs[2 * kt + 1][1], pah[2], pal[2]);
            split_pack(cs[2 * kt + 1][2], cs[2 * kt + 1][3], pah[3], pal[3]);
#pragma unroll
            for (int nt = 0; nt < 4; nt++) {
                uint32_t vh[4], vl[4];
                uint32_t off = (uint32_t)((kt * 16 + rA) * 128 + nt * 32 + cb16);
                off ^= (off >> 3) & 0x70;
                ldsm_x4_t(vh, st + AT_VHI + off);
                ldsm_x4_t(vl, st + AT_VLO + off);
                mma_bf16(co[nt * 2 + 0], pah, vh[0], vh[1]);
                mma_bf16(co[nt * 2 + 0], pah, vl[0], vl[1]);
                mma_bf16(co[nt * 2 + 0], pal, vh[0], vh[1]);
                mma_bf16(co[nt * 2 + 1], pah, vh[2], vh[3]);
                mma_bf16(co[nt * 2 + 1], pah, vl[2], vl[3]);
                mma_bf16(co[nt * 2 + 1], pal, vh[2], vh[3]);
            }
        }
    }

    // ---- epilogue: ctx -> bf16 hi/lo (FIX: batch offset in row0) ----
    const float inv0 = 1.f / l_i[0], inv1 = 1.f / l_i[1];
    const int row0 = b * S_LEN + qt * 128 + wm + (lane >> 2);
    const int colb = h * HDIM + 2 * (lane & 3);
#pragma unroll
    for (int nf = 0; nf < 8; nf++) {
        const int col = colb + nf * 8;
        uint32_t h0, l0, h1, l1;
        split_pack(co[nf][0] * inv0, co[nf][1] * inv0, h0, l0);
        split_pack(co[nf][2] * inv1, co[nf][3] * inv1, h1, l1);
        *(uint32_t*)&g_Chi[(size_t)row0 * DMODEL + col] = h0;
        *(uint32_t*)&g_Clo[(size_t)row0 * DMODEL + col] = l0;
        *(uint32_t*)&g_Chi[(size_t)(row0 + 8) * DMODEL + col] = h1;
        *(uint32_t*)&g_Clo[(size_t)(row0 + 8) * DMODEL + col] = l1;
    }
}

// ---------------------------------------------------------------------------
extern "C" void kernel_launch(void* const* d_in, const int* in_sizes, int n_in,
                              void* d_out, int out_size)
{
    const float* x  = (const float*)d_in[0];
    const float* Wq = (const float*)d_in[1];
    const float* Wk = (const float*)d_in[2];
    const float* Wv = (const float*)d_in[3];
    const float* Wo = (const float*)d_in[4];
    const float* bo = (const float*)d_in[5];
    float* out = (float*)d_out;

    cudaFuncSetAttribute(gemm_kernel, cudaFuncAttributeMaxDynamicSharedMemorySize, GS_TOTAL);
    cudaFuncSetAttribute(attn_kernel, cudaFuncAttributeMaxDynamicSharedMemorySize, AT_TOTAL);

    split_kernel<<<(MROWS * DMODEL + 255) / 256, 256>>>(x, MROWS * DMODEL, 0);
    split_kernel<<<(DMODEL * DMODEL + 255) / 256, 256>>>(Wo, DMODEL * DMODEL, 1);
    tsplit_kernel<<<dim3(32, 32, 3), dim3(32, 8)>>>(Wq, Wk, Wv);

    gemm_kernel<<<dim3(DMODEL / 128, MROWS / 128, 3), 256, GS_TOTAL>>>(0, nullptr, nullptr);

    attn_kernel<<<dim3(S_LEN / 128, BATCH * NHEADS), 256, AT_TOTAL>>>();

    gemm_kernel<<<dim3(DMODEL / 128, MROWS / 128, 1), 256, GS_TOTAL>>>(1, out, bo);
}

// round 9
// speedup vs baseline: 3.1719x; 1.0984x over previous
#include <cuda_runtime.h>
#include <cuda_bf16.h>
#include <math.h>
#include <stdint.h>

#define S_LEN   2048
#define DMODEL  1024
#define NHEADS  16
#define HDIM    64
#define BATCH   2
#define MROWS   (BATCH * S_LEN)   // 4096

extern __shared__ __align__(128) float dyn_smem[];

// ---------------------------------------------------------------------------
// Global scratch
// ---------------------------------------------------------------------------
__device__ __align__(128) __nv_bfloat16 g_Xhi[MROWS * DMODEL];
__device__ __align__(128) __nv_bfloat16 g_Xlo[MROWS * DMODEL];
__device__ __align__(128) __nv_bfloat16 g_Wthi[3 * DMODEL * DMODEL];
__device__ __align__(128) __nv_bfloat16 g_Wtlo[3 * DMODEL * DMODEL];
__device__ __align__(128) __nv_bfloat16 g_Wohi[DMODEL * DMODEL];
__device__ __align__(128) __nv_bfloat16 g_Wolo[DMODEL * DMODEL];
__device__ __align__(128) __nv_bfloat16 g_Chi[MROWS * DMODEL];
__device__ __align__(128) __nv_bfloat16 g_Clo[MROWS * DMODEL];
__device__ __align__(128) __nv_bfloat16 g_QKVhi[3 * MROWS * DMODEL];  // Q pre-scaled by 0.125
__device__ __align__(128) __nv_bfloat16 g_QKVlo[3 * MROWS * DMODEL];

// ---------------------------------------------------------------------------
// Helpers
// ---------------------------------------------------------------------------
__device__ __forceinline__ uint32_t smem_u32(const void* p) {
    uint32_t a;
    asm("{ .reg .u64 t; cvta.to.shared.u64 t, %1; cvt.u32.u64 %0, t; }" : "=r"(a) : "l"(p));
    return a;
}
__device__ __forceinline__ void ldsm_x4(uint32_t* r, uint32_t addr) {
    asm volatile("ldmatrix.sync.aligned.m8n8.x4.shared.b16 {%0,%1,%2,%3}, [%4];"
                 : "=r"(r[0]), "=r"(r[1]), "=r"(r[2]), "=r"(r[3]) : "r"(addr));
}
__device__ __forceinline__ void ldsm_x4_t(uint32_t* r, uint32_t addr) {
    asm volatile("ldmatrix.sync.aligned.m8n8.x4.trans.shared.b16 {%0,%1,%2,%3}, [%4];"
                 : "=r"(r[0]), "=r"(r[1]), "=r"(r[2]), "=r"(r[3]) : "r"(addr));
}
__device__ __forceinline__ void mma_bf16(float* c, const uint32_t* a, uint32_t b0, uint32_t b1) {
    asm volatile(
        "mma.sync.aligned.m16n8k16.row.col.f32.bf16.bf16.f32 "
        "{%0,%1,%2,%3},{%4,%5,%6,%7},{%8,%9},{%0,%1,%2,%3};"
        : "+f"(c[0]), "+f"(c[1]), "+f"(c[2]), "+f"(c[3])
        : "r"(a[0]), "r"(a[1]), "r"(a[2]), "r"(a[3]), "r"(b0), "r"(b1));
}
// split-pack: out_hi/out_lo get bf16 hi/lo pairs of (a,b)
__device__ __forceinline__ void split_pack(float a, float b, uint32_t& oh, uint32_t& ol) {
    __nv_bfloat16 ha = __float2bfloat16(a), hb = __float2bfloat16(b);
    float la = a - __bfloat162float(ha), lb = b - __bfloat162float(hb);
    __nv_bfloat162 th, tl;
    th.x = ha; th.y = hb;
    tl.x = __float2bfloat16(la); tl.y = __float2bfloat16(lb);
    oh = *(uint32_t*)&th; ol = *(uint32_t*)&tl;
}

// ---------------------------------------------------------------------------
// Pre-pass splits
// ---------------------------------------------------------------------------
__global__ void split_kernel(const float* __restrict__ src, int n, int mode) {
    __nv_bfloat16* hi = mode ? g_Wohi : g_Xhi;
    __nv_bfloat16* lo = mode ? g_Wolo : g_Xlo;
    int i = blockIdx.x * 256 + threadIdx.x;
    if (i < n) {
        float a = src[i];
        __nv_bfloat16 h = __float2bfloat16(a);
        hi[i] = h;
        lo[i] = __float2bfloat16(a - __bfloat162float(h));
    }
}

__global__ void tsplit_kernel(const float* __restrict__ Wq,
                              const float* __restrict__ Wk,
                              const float* __restrict__ Wv) {
    const float* W = (blockIdx.z == 0) ? Wq : (blockIdx.z == 1) ? Wk : Wv;
    __nv_bfloat16* Hi = g_Wthi + (size_t)blockIdx.z * DMODEL * DMODEL;
    __nv_bfloat16* Lo = g_Wtlo + (size_t)blockIdx.z * DMODEL * DMODEL;
    __shared__ float t[32][33];
    const int k0 = blockIdx.y * 32, n0 = blockIdx.x * 32;
    const int tx = threadIdx.x, ty = threadIdx.y;
#pragma unroll
    for (int r = 0; r < 4; r++)
        t[ty + 8 * r][tx] = W[(size_t)(k0 + ty + 8 * r) * DMODEL + n0 + tx];
    __syncthreads();
#pragma unroll
    for (int r = 0; r < 4; r++) {
        float a = t[tx][ty + 8 * r];
        size_t idx = (size_t)(n0 + ty + 8 * r) * DMODEL + k0 + tx;
        __nv_bfloat16 h = __float2bfloat16(a);
        Hi[idx] = h;
        Lo[idx] = __float2bfloat16(a - __bfloat162float(h));
    }
}

// ---------------------------------------------------------------------------
// Tile loaders (row stride DMODEL, SW128 swizzle, 16B cp.async)
// ---------------------------------------------------------------------------
__device__ __forceinline__ void at_load64(uint32_t sdst, const __nv_bfloat16* g, int tid) {
#pragma unroll
    for (int t = 0; t < 2; t++) {
        int cid = t * 256 + tid;
        int r = cid >> 3, ch = cid & 7;
        uint32_t off = (uint32_t)(r * 128 + ch * 16);
        off ^= (off >> 3) & 0x70;
        const char* src = (const char*)(g + (size_t)r * DMODEL) + ch * 16;
        asm volatile("cp.async.cg.shared.global [%0], [%1], 16;" :: "r"(sdst + off), "l"(src));
    }
}
__device__ __forceinline__ void at_load128(uint32_t sdst, const __nv_bfloat16* g, int tid) {
#pragma unroll
    for (int t = 0; t < 4; t++) {
        int cid = t * 256 + tid;
        int r = cid >> 3, ch = cid & 7;
        uint32_t off = (uint32_t)(r * 128 + ch * 16);
        off ^= (off >> 3) & 0x70;
        const char* src = (const char*)(g + (size_t)r * DMODEL) + ch * 16;
        asm volatile("cp.async.cg.shared.global [%0], [%1], 16;" :: "r"(sdst + off), "l"(src));
    }
}

// ---------------------------------------------------------------------------
// bf16 3x mma GEMM, 128x64 CTA tile, 8 warps x (16x64), 2 CTAs/SM.
// smem/stage: Ahi 16K | Alo 16K | Bhi 8K | Blo 8K = 48K; 2 stages = 96K
// ---------------------------------------------------------------------------
#define GS_STAGE 49152
#define GS_AHI   0
#define GS_ALO   16384
#define GS_BHI   32768
#define GS_BLO   40960
#define GS_TOTAL (2 * GS_STAGE)   // 98304

__global__ __launch_bounds__(256, 2) void gemm_kernel(int mode, float* __restrict__ outp,
                                                      const float* __restrict__ biasp) {
    uint32_t sb = smem_u32(dyn_smem);
    const int tid = threadIdx.x, lane = tid & 31, wid = tid >> 5;
    const int wm = wid * 16;
    const int rowBase = blockIdx.y * 128;
    const int colBase = blockIdx.x * 64;
    const int z = blockIdx.z;
    const int rA = lane & 15, cb16 = (lane >> 4) << 4;

    const __nv_bfloat16 *Ah, *Al, *Bh, *Bl;
    if (mode == 0) {
        Ah = g_Xhi; Al = g_Xlo;
        Bh = g_Wthi + (size_t)z * DMODEL * DMODEL;
        Bl = g_Wtlo + (size_t)z * DMODEL * DMODEL;
    } else {
        Ah = g_Chi; Al = g_Clo;
        Bh = g_Wohi; Bl = g_Wolo;
    }
    Ah += (size_t)rowBase * DMODEL;
    Al += (size_t)rowBase * DMODEL;
    Bh += (size_t)colBase * DMODEL;
    Bl += (size_t)colBase * DMODEL;

    float c[8][4];
#pragma unroll
    for (int i = 0; i < 8; i++)
#pragma unroll
        for (int j = 0; j < 4; j++) c[i][j] = 0.f;

    at_load128(sb + GS_AHI, Ah, tid);
    at_load128(sb + GS_ALO, Al, tid);
    at_load64(sb + GS_BHI, Bh, tid);
    at_load64(sb + GS_BLO, Bl, tid);
    asm volatile("cp.async.commit_group;");

    for (int ck = 0; ck < 16; ck++) {
        const int s = ck & 1;
        if (ck > 0) __syncthreads();
        if (ck + 1 < 16) {
            uint32_t st = sb + (uint32_t)((ck + 1) & 1) * GS_STAGE;
            const int k0 = (ck + 1) * 64;
            at_load128(st + GS_AHI, Ah + k0, tid);
            at_load128(st + GS_ALO, Al + k0, tid);
            at_load64(st + GS_BHI, Bh + k0, tid);
            at_load64(st + GS_BLO, Bl + k0, tid);
            asm volatile("cp.async.commit_group;");
            asm volatile("cp.async.wait_group 1;");
        } else {
            asm volatile("cp.async.wait_group 0;");
        }
        __syncthreads();

        const uint32_t aHi = sb + (uint32_t)s * GS_STAGE + GS_AHI;
        const uint32_t aLo = sb + (uint32_t)s * GS_STAGE + GS_ALO;
        const uint32_t bHi = sb + (uint32_t)s * GS_STAGE + GS_BHI;
        const uint32_t bLo = sb + (uint32_t)s * GS_STAGE + GS_BLO;

#pragma unroll
        for (int ks = 0; ks < 4; ks++) {
            const int cb = ks * 32 + cb16;
            uint32_t AhF[4], AlF[4];
            {
                uint32_t off = (uint32_t)((wm + rA) * 128 + cb);
                off ^= (off >> 3) & 0x70;
                ldsm_x4(AhF, aHi + off);
                ldsm_x4(AlF, aLo + off);
            }
#pragma unroll
            for (int nt = 0; nt < 4; nt++) {
                uint32_t bh[4], bl[4];
                uint32_t off = (uint32_t)((nt * 16 + rA) * 128 + cb);
                off ^= (off >> 3) & 0x70;
                ldsm_x4(bh, bHi + off);
                ldsm_x4(bl, bLo + off);
#pragma unroll
                for (int o = 0; o < 2; o++) {
                    mma_bf16(c[nt * 2 + o], AhF, bh[o], bh[o + 2]);
                    mma_bf16(c[nt * 2 + o], AhF, bl[o], bl[o + 2]);
                    mma_bf16(c[nt * 2 + o], AlF, bh[o], bh[o + 2]);
                }
            }
        }
    }

    const int r0 = rowBase + wm + (lane >> 2);
    const int cl = 2 * (lane & 3);
    if (mode == 0) {
        const float scale = (z == 0) ? 0.125f : 1.0f;   // fold softmax scale into Q (exact)
        __nv_bfloat16* Hi = g_QKVhi + (size_t)z * MROWS * DMODEL;
        __nv_bfloat16* Lo = g_QKVlo + (size_t)z * MROWS * DMODEL;
#pragma unroll
        for (int nf = 0; nf < 8; nf++) {
            const int col = colBase + nf * 8 + cl;
            uint32_t h0, l0, h1, l1;
            split_pack(c[nf][0] * scale, c[nf][1] * scale, h0, l0);
            split_pack(c[nf][2] * scale, c[nf][3] * scale, h1, l1);
            *(uint32_t*)&Hi[(size_t)r0 * DMODEL + col] = h0;
            *(uint32_t*)&Lo[(size_t)r0 * DMODEL + col] = l0;
            *(uint32_t*)&Hi[(size_t)(r0 + 8) * DMODEL + col] = h1;
            *(uint32_t*)&Lo[(size_t)(r0 + 8) * DMODEL + col] = l1;
        }
    } else {
#pragma unroll
        for (int nf = 0; nf < 8; nf++) {
            const int col = colBase + nf * 8 + cl;
            const float b0 = biasp[col], b1 = biasp[col + 1];
            float2 v0 = make_float2(c[nf][0] + b0, c[nf][1] + b1);
            float2 v1 = make_float2(c[nf][2] + b0, c[nf][3] + b1);
            *(float2*)&outp[(size_t)r0 * DMODEL + col] = v0;
            *(float2*)&outp[(size_t)(r0 + 8) * DMODEL + col] = v1;
        }
    }
}

// ---------------------------------------------------------------------------
// Tensor-core causal flash attention (unchanged from R8).
// ---------------------------------------------------------------------------
#define AT_STAGE 32768
#define AT_KHI   0
#define AT_KLO   8192
#define AT_VHI   16384
#define AT_VLO   24576
#define AT_QHI   65536
#define AT_QLO   81920
#define AT_TOTAL 98304

__global__ __launch_bounds__(256) void attn_kernel() {
    uint32_t sb = smem_u32(dyn_smem);
    const int tid = threadIdx.x, lane = tid & 31, wid = tid >> 5;
    const int qt = blockIdx.x, bh = blockIdx.y;
    const int b = bh >> 4, h = bh & 15;
    const int wm = wid * 16;
    const int rA = lane & 15, cb16 = (lane >> 4) << 4;
    const int jmax = 2 * qt + 1;

    const size_t qoff = ((size_t)b * S_LEN + qt * 128) * DMODEL + h * HDIM;
    const __nv_bfloat16* Qh_g = g_QKVhi + qoff;
    const __nv_bfloat16* Ql_g = g_QKVlo + qoff;
    const size_t kvbase = (size_t)b * S_LEN * DMODEL + h * HDIM;
    const __nv_bfloat16* Kh_g = g_QKVhi + (size_t)MROWS * DMODEL + kvbase;
    const __nv_bfloat16* Kl_g = g_QKVlo + (size_t)MROWS * DMODEL + kvbase;
    const __nv_bfloat16* Vh_g = g_QKVhi + (size_t)2 * MROWS * DMODEL + kvbase;
    const __nv_bfloat16* Vl_g = g_QKVlo + (size_t)2 * MROWS * DMODEL + kvbase;

    at_load128(sb + AT_QHI, Qh_g, tid);
    at_load128(sb + AT_QLO, Ql_g, tid);
    at_load64(sb + AT_KHI, Kh_g, tid);
    at_load64(sb + AT_KLO, Kl_g, tid);
    at_load64(sb + AT_VHI, Vh_g, tid);
    at_load64(sb + AT_VLO, Vl_g, tid);
    asm volatile("cp.async.commit_group;");

    float co[8][4];
#pragma unroll
    for (int i = 0; i < 8; i++)
#pragma unroll
        for (int j = 0; j < 4; j++) co[i][j] = 0.f;
    float m_i[2] = {-INFINITY, -INFINITY};
    float l_i[2] = {0.f, 0.f};
    uint32_t QhF[4][4], QlF[4][4];

    for (int j = 0; j <= jmax; j++) {
        __syncthreads();
        if (j + 1 <= jmax) {
            uint32_t st = sb + (uint32_t)((j + 1) & 1) * AT_STAGE;
            const size_t ro = (size_t)(j + 1) * 64 * DMODEL;
            at_load64(st + AT_KHI, Kh_g + ro, tid);
            at_load64(st + AT_KLO, Kl_g + ro, tid);
            at_load64(st + AT_VHI, Vh_g + ro, tid);
            at_load64(st + AT_VLO, Vl_g + ro, tid);
            asm volatile("cp.async.commit_group;");
            asm volatile("cp.async.wait_group 1;");
        } else {
            asm volatile("cp.async.wait_group 0;");
        }
        __syncthreads();

        if (j == 0) {
#pragma unroll
            for (int ks = 0; ks < 4; ks++) {
                uint32_t off = (uint32_t)((wm + rA) * 128 + ks * 32 + cb16);
                off ^= (off >> 3) & 0x70;
                ldsm_x4(QhF[ks], sb + AT_QHI + off);
                ldsm_x4(QlF[ks], sb + AT_QLO + off);
            }
        }

        const int qmin = qt * 128 + wm;
        if (j * 64 > qmin + 15) continue;

        const uint32_t st = sb + (uint32_t)(j & 1) * AT_STAGE;

        float cs[8][4];
#pragma unroll
        for (int i = 0; i < 8; i++)
#pragma unroll
            for (int e = 0; e < 4; e++) cs[i][e] = 0.f;
#pragma unroll
        for (int ks = 0; ks < 4; ks++) {
#pragma unroll
            for (int nt = 0; nt < 4; nt++) {
                uint32_t kh[4], kl[4];
                uint32_t off = (uint32_t)((nt * 16 + rA) * 128 + ks * 32 + cb16);
                off ^= (off >> 3) & 0x70;
                ldsm_x4(kh, st + AT_KHI + off);
                ldsm_x4(kl, st + AT_KLO + off);
#pragma unroll
                for (int o = 0; o < 2; o++) {
                    mma_bf16(cs[nt * 2 + o], QhF[ks], kh[o], kh[o + 2]);
                    mma_bf16(cs[nt * 2 + o], QhF[ks], kl[o], kl[o + 2]);
                    mma_bf16(cs[nt * 2 + o], QlF[ks], kh[o], kh[o + 2]);
                }
            }
        }

        if (j * 64 + 63 > qmin) {
            const int r0 = lane >> 2, c0 = 2 * (lane & 3);
#pragma unroll
            for (int nf = 0; nf < 8; nf++) {
#pragma unroll
                for (int e = 0; e < 4; e++) {
                    const int col = nf * 8 + c0 + (e & 1);
                    const int row = r0 + ((e >> 1) * 8);
                    if (j * 64 + col > qmin + row) cs[nf][e] = -1e30f;
                }
            }
        }

        float mx0 = -INFINITY, mx1 = -INFINITY;
#pragma unroll
        for (int nf = 0; nf < 8; nf++) {
            mx0 = fmaxf(mx0, fmaxf(cs[nf][0], cs[nf][1]));
            mx1 = fmaxf(mx1, fmaxf(cs[nf][2], cs[nf][3]));
        }
        mx0 = fmaxf(mx0, __shfl_xor_sync(0xffffffffu, mx0, 1));
        mx0 = fmaxf(mx0, __shfl_xor_sync(0xffffffffu, mx0, 2));
        mx1 = fmaxf(mx1, __shfl_xor_sync(0xffffffffu, mx1, 1));
        mx1 = fmaxf(mx1, __shfl_xor_sync(0xffffffffu, mx1, 2));
        const float mn0 = fmaxf(m_i[0], mx0), mn1 = fmaxf(m_i[1], mx1);
        const float corr0 = __expf(m_i[0] - mn0), corr1 = __expf(m_i[1] - mn1);
        float rs0 = 0.f, rs1 = 0.f;
#pragma unroll
        for (int nf = 0; nf < 8; nf++) {
            cs[nf][0] = __expf(cs[nf][0] - mn0); rs0 += cs[nf][0];
            cs[nf][1] = __expf(cs[nf][1] - mn0); rs0 += cs[nf][1];
            cs[nf][2] = __expf(cs[nf][2] - mn1); rs1 += cs[nf][2];
            cs[nf][3] = __expf(cs[nf][3] - mn1); rs1 += cs[nf][3];
        }
        rs0 += __shfl_xor_sync(0xffffffffu, rs0, 1);
        rs0 += __shfl_xor_sync(0xffffffffu, rs0, 2);
        rs1 += __shfl_xor_sync(0xffffffffu, rs1, 1);
        rs1 += __shfl_xor_sync(0xffffffffu, rs1, 2);
        l_i[0] = l_i[0] * corr0 + rs0; m_i[0] = mn0;
        l_i[1] = l_i[1] * corr1 + rs1; m_i[1] = mn1;
#pragma unroll
        for (int nf = 0; nf < 8; nf++) {
            co[nf][0] *= corr0; co[nf][1] *= corr0;
            co[nf][2] *= corr1; co[nf][3] *= corr1;
        }

#pragma unroll
        for (int kt = 0; kt < 4; kt++) {
            uint32_t pah[4], pal[4];
            split_pack(cs[2 * kt][0],     cs[2 * kt][1],     pah[0], pal[0]);
            split_pack(cs[2 * kt][2],     cs[2 * kt][3],     pah[1], pal[1]);
            split_pack(cs[2 * kt + 1][0], cs[2 * kt + 1][1], pah[2], pal[2]);
            split_pack(cs[2 * kt + 1][2], cs[2 * kt + 1][3], pah[3], pal[3]);
#pragma unroll
            for (int nt = 0; nt < 4; nt++) {
                uint32_t vh[4], vl[4];
                uint32_t off = (uint32_t)((kt * 16 + rA) * 128 + nt * 32 + cb16);
                off ^= (off >> 3) & 0x70;
                ldsm_x4_t(vh, st + AT_VHI + off);
                ldsm_x4_t(vl, st + AT_VLO + off);
                mma_bf16(co[nt * 2 + 0], pah, vh[0], vh[1]);
                mma_bf16(co[nt * 2 + 0], pah, vl[0], vl[1]);
                mma_bf16(co[nt * 2 + 0], pal, vh[0], vh[1]);
                mma_bf16(co[nt * 2 + 1], pah, vh[2], vh[3]);
                mma_bf16(co[nt * 2 + 1], pah, vl[2], vl[3]);
                mma_bf16(co[nt * 2 + 1], pal, vh[2], vh[3]);
            }
        }
    }

    const float inv0 = 1.f / l_i[0], inv1 = 1.f / l_i[1];
    const int row0 = b * S_LEN + qt * 128 + wm + (lane >> 2);
    const int colb = h * HDIM + 2 * (lane & 3);
#pragma unroll
    for (int nf = 0; nf < 8; nf++) {
        const int col = colb + nf * 8;
        uint32_t h0, l0, h1, l1;
        split_pack(co[nf][0] * inv0, co[nf][1] * inv0, h0, l0);
        split_pack(co[nf][2] * inv1, co[nf][3] * inv1, h1, l1);
        *(uint32_t*)&g_Chi[(size_t)row0 * DMODEL + col] = h0;
        *(uint32_t*)&g_Clo[(size_t)row0 * DMODEL + col] = l0;
        *(uint32_t*)&g_Chi[(size_t)(row0 + 8) * DMODEL + col] = h1;
        *(uint32_t*)&g_Clo[(size_t)(row0 + 8) * DMODEL + col] = l1;
    }
}

// ---------------------------------------------------------------------------
extern "C" void kernel_launch(void* const* d_in, const int* in_sizes, int n_in,
                              void* d_out, int out_size)
{
    const float* x  = (const float*)d_in[0];
    const float* Wq = (const float*)d_in[1];
    const float* Wk = (const float*)d_in[2];
    const float* Wv = (const float*)d_in[3];
    const float* Wo = (const float*)d_in[4];
    const float* bo = (const float*)d_in[5];
    float* out = (float*)d_out;

    cudaFuncSetAttribute(gemm_kernel, cudaFuncAttributeMaxDynamicSharedMemorySize, GS_TOTAL);
    cudaFuncSetAttribute(attn_kernel, cudaFuncAttributeMaxDynamicSharedMemorySize, AT_TOTAL);

    split_kernel<<<(MROWS * DMODEL + 255) / 256, 256>>>(x, MROWS * DMODEL, 0);
    split_kernel<<<(DMODEL * DMODEL + 255) / 256, 256>>>(Wo, DMODEL * DMODEL, 1);
    tsplit_kernel<<<dim3(32, 32, 3), dim3(32, 8)>>>(Wq, Wk, Wv);

    // QKV projections: 128x64 tiles, 2 CTAs/SM
    gemm_kernel<<<dim3(DMODEL / 64, MROWS / 128, 3), 256, GS_TOTAL>>>(0, nullptr, nullptr);

    attn_kernel<<<dim3(S_LEN / 128, BATCH * NHEADS), 256, AT_TOTAL>>>();

    gemm_kernel<<<dim3(DMODEL / 64, MROWS / 128, 1), 256, GS_TOTAL>>>(1, out, bo);
}